// round 12
// baseline (speedup 1.0000x reference)
#include <cuda_runtime.h>
#include <cuda_bf16.h>
#include <math.h>

#define NN      100000
#define F_IN    256
#define HID     64
#define H1      8
#define C1      8
#define NC      40
#define E_MAX   1700000
#define NEG_SLOPE 0.2f
#define AST     132

// ---------------- packed f32x2 helpers ----------------------------------------
__device__ __forceinline__ unsigned long long ffma2(
    unsigned long long a, unsigned long long b, unsigned long long c) {
    unsigned long long d;
    asm("fma.rn.f32x2 %0, %1, %2, %3;" : "=l"(d) : "l"(a), "l"(b), "l"(c));
    return d;
}
__device__ __forceinline__ unsigned long long pack2(float lo, float hi) {
    unsigned long long d;
    asm("mov.b64 %0, {%1, %2};" : "=l"(d) : "f"(lo), "f"(hi));
    return d;
}
__device__ __forceinline__ void unpack2(unsigned long long v, float& lo, float& hi) {
    asm("mov.b64 {%0, %1}, %2;" : "=f"(lo), "=f"(hi) : "l"(v));
}

// ---------------- scratch -----------------------------------------------------
__device__ int   g_is64;
__device__ int   g_deg[NN];
__device__ int   g_rowptr[NN + 1];
__device__ int   g_fill[NN];
__device__ int   g_col[E_MAX];
__device__ int   g_bsum[256];
__device__ float g_h1[(long)NN * HID];
__device__ float g_as1[NN * H1];
__device__ float g_ad1[NN * H1];
__device__ float g_h2[(long)NN * NC];
__device__ float g_as2[NN];
__device__ float g_ad2[NN];

// -------- init: zero degrees + edge dtype detection (block 0) -----------------
__global__ void k_init(const void* ei, int EC) {
    int i = blockIdx.x * blockDim.x + threadIdx.x;
    if (i < NN) g_deg[i] = 0;
    if (blockIdx.x == 0) {
        __shared__ int bad;
        if (threadIdx.x == 0) bad = 0;
        __syncthreads();
        const long long* p = (const long long*)ei;
        int n = EC < 256 ? EC : 256;
        if ((int)threadIdx.x < n) {
            long long v = p[threadIdx.x];
            if (v < 0 || v >= NN) atomicExch(&bad, 1);
        }
        __syncthreads();
        if (threadIdx.x == 0) g_is64 = bad ? 0 : 1;
    }
}

__device__ __forceinline__ int edge_at(const void* ei, int idx) {
    return g_is64 ? (int)((const long long*)ei)[idx] : ((const int*)ei)[idx];
}

// ---------------- CSR build ---------------------------------------------------
__global__ void k_hist(const void* ei, int EC) {
    int i = blockIdx.x * blockDim.x + threadIdx.x;
    if (i < EC) {
        int d = edge_at(ei, EC + i);
        if (d >= 0 && d < NN) atomicAdd(&g_deg[d], 1);
    }
}

__global__ void k_scan_block() {
    __shared__ int ws[32];
    int tid = threadIdx.x;
    int gid = blockIdx.x * 1024 + tid;
    int v = (gid < NN) ? g_deg[gid] : 0;
    int x = v;
    #pragma unroll
    for (int o = 1; o < 32; o <<= 1) {
        int t = __shfl_up_sync(0xffffffffu, x, o);
        if ((tid & 31) >= o) x += t;
    }
    if ((tid & 31) == 31) ws[tid >> 5] = x;
    __syncthreads();
    if (tid < 32) {
        int w = ws[tid];
        int y = w;
        #pragma unroll
        for (int o = 1; o < 32; o <<= 1) {
            int t = __shfl_up_sync(0xffffffffu, y, o);
            if (tid >= o) y += t;
        }
        ws[tid] = y - w;
    }
    __syncthreads();
    int incl = x + ws[tid >> 5];
    if (gid < NN) g_rowptr[gid] = incl - v;
    if (tid == 1023) g_bsum[blockIdx.x] = incl;
}

__global__ void k_scan_tops(int nblocks) {
    int lane = threadIdx.x;
    int run = 0;
    for (int base = 0; base < nblocks; base += 32) {
        int idx = base + lane;
        int v = (idx < nblocks) ? g_bsum[idx] : 0;
        int x = v;
        #pragma unroll
        for (int o = 1; o < 32; o <<= 1) {
            int t = __shfl_up_sync(0xffffffffu, x, o);
            if (lane >= o) x += t;
        }
        if (idx < nblocks) g_bsum[idx] = run + x - v;
        run += __shfl_sync(0xffffffffu, x, 31);
    }
}

__global__ void k_scan_fix(int EC) {
    int gid = blockIdx.x * 1024 + threadIdx.x;
    if (gid < NN) {
        int v = g_rowptr[gid] + g_bsum[gid >> 10];
        g_rowptr[gid] = v;
        g_fill[gid] = v;
    }
    if (gid == 0) g_rowptr[NN] = EC;
}

__global__ void k_scatter(const void* ei, int EC) {
    int i = blockIdx.x * blockDim.x + threadIdx.x;
    if (i < EC) {
        int s = edge_at(ei, i);
        int d = edge_at(ei, EC + i);
        if (d >= 0 && d < NN) {
            int p = atomicAdd(&g_fill[d], 1);
            if (p >= 0 && p < E_MAX) g_col[p] = s;
        }
    }
}

// ------- GEMM1 (128x64 tile, FFMA2 inner) + fused alpha epilogue --------------
__global__ void __launch_bounds__(256) k_gemm1(
    const float* __restrict__ X, const float* __restrict__ W,
    const float* __restrict__ att_s, const float* __restrict__ att_d) {
    __shared__ __align__(16) float sm[128 * 65];
    float* Ast = sm;
    float* Bs  = sm + 32 * AST;
    int tid = threadIdx.x;
    int r0 = blockIdx.x * 128;
    int tx = tid & 15, ty = tid >> 4;

    unsigned long long acc2[4][4];
    unsigned long long z = pack2(0.f, 0.f);
    #pragma unroll
    for (int p = 0; p < 4; p++)
        #pragma unroll
        for (int c = 0; c < 4; c++) acc2[p][c] = z;

    for (int k0 = 0; k0 < F_IN; k0 += 32) {
        #pragma unroll
        for (int l = 0; l < 4; l++) {
            int slot = tid + l * 256;
            int row = slot >> 3;
            int f4 = slot & 7;
            int gr = r0 + row;
            float4 v = make_float4(0.f, 0.f, 0.f, 0.f);
            if (gr < NN) v = *(const float4*)(X + (long)gr * F_IN + k0 + f4 * 4);
            Ast[(f4 * 4 + 0) * AST + row] = v.x;
            Ast[(f4 * 4 + 1) * AST + row] = v.y;
            Ast[(f4 * 4 + 2) * AST + row] = v.z;
            Ast[(f4 * 4 + 3) * AST + row] = v.w;
        }
        #pragma unroll
        for (int l = 0; l < 2; l++) {
            int slot = tid + l * 256;
            int kk = slot >> 4;
            int cv = slot & 15;
            *(float4*)&Bs[kk * 64 + cv * 4] = *(const float4*)(W + (k0 + kk) * HID + cv * 4);
        }
        __syncthreads();
        #pragma unroll
        for (int kk = 0; kk < 32; kk++) {
            float4 bv = *(const float4*)&Bs[kk * 64 + tx * 4];
            unsigned long long br[4];
            br[0] = pack2(bv.x, bv.x);
            br[1] = pack2(bv.y, bv.y);
            br[2] = pack2(bv.z, bv.z);
            br[3] = pack2(bv.w, bv.w);
            const float* ab = Ast + kk * AST + ty * 8;
            #pragma unroll
            for (int p = 0; p < 4; p++) {
                unsigned long long ap = *(const unsigned long long*)(ab + 2 * p);
                acc2[p][0] = ffma2(ap, br[0], acc2[p][0]);
                acc2[p][1] = ffma2(ap, br[1], acc2[p][1]);
                acc2[p][2] = ffma2(ap, br[2], acc2[p][2]);
                acc2[p][3] = ffma2(ap, br[3], acc2[p][3]);
            }
        }
        __syncthreads();
    }

    float* hbuf = sm;
    #pragma unroll
    for (int p = 0; p < 4; p++) {
        float lo[4], hi[4];
        #pragma unroll
        for (int c = 0; c < 4; c++) unpack2(acc2[p][c], lo[c], hi[c]);
        int lr = ty * 8 + 2 * p;
        int gr = r0 + lr;
        #pragma unroll
        for (int c = 0; c < 4; c++) {
            hbuf[lr * 65 + tx * 4 + c] = lo[c];
            hbuf[(lr + 1) * 65 + tx * 4 + c] = hi[c];
        }
        if (gr < NN) {
            #pragma unroll
            for (int c = 0; c < 4; c++)
                g_h1[(long)gr * HID + tx * 4 + c] = lo[c];
        }
        if (gr + 1 < NN) {
            #pragma unroll
            for (int c = 0; c < 4; c++)
                g_h1[(long)(gr + 1) * HID + tx * 4 + c] = hi[c];
        }
    }
    __syncthreads();

    #pragma unroll
    for (int t = 0; t < 4; t++) {
        int item = tid + t * 256;
        int lr = item >> 3, h = item & 7;
        int gr = r0 + lr;
        if (gr < NN) {
            const float* hp = hbuf + lr * 65 + h * C1;
            float as = 0.f, ad = 0.f;
            #pragma unroll
            for (int c = 0; c < C1; c++) {
                float hv = hp[c];
                as += hv * __ldg(att_s + h * C1 + c);
                ad += hv * __ldg(att_d + h * C1 + c);
            }
            g_as1[gr * H1 + h] = as;
            g_ad1[gr * H1 + h] = ad;
        }
    }
}

// ---- fused agg1 + elu + GEMM2 + alpha2; half-warp edge splitting -------------
// Lanes split: half = lane>>4 processes edges i ≡ half (mod 2); sub-lane sl =
// lane&15 covers channels 4sl..4sl+3 (head sl>>1). Halves combine via one
// shfl_xor(16) after the loop. Serial chain per warp halves vs round 7.
__global__ void __launch_bounds__(256) k_agg1g2(
    const float* __restrict__ b1, const float* __restrict__ W2,
    const float* __restrict__ att_s2, const float* __restrict__ att_d2) {
    __shared__ __align__(16) unsigned long long Wp[HID][NC / 2];
    __shared__ float Sa[NC], Sd[NC];
    __shared__ __align__(16) float hb[8][HID];

    int tid = threadIdx.x;
    for (int i = tid; i < HID * (NC / 2); i += 256) {
        int k = i / (NC / 2), j = i % (NC / 2);
        float2 w = *(const float2*)(W2 + k * NC + 2 * j);
        Wp[k][j] = pack2(w.x, w.y);
    }
    if (tid < NC) { Sa[tid] = __ldg(att_s2 + tid); Sd[tid] = __ldg(att_d2 + tid); }
    __syncthreads();

    int warp = (blockIdx.x * blockDim.x + tid) >> 5;
    int wslot = (tid >> 5) & 7;
    int lane = tid & 31;
    if (warp >= NN) return;
    int d = warp;
    int start = g_rowptr[d], end = g_rowptr[d + 1];
    int half = lane >> 4;
    int sl = lane & 15;
    int h = sl >> 1;
    float ad = __ldg(g_ad1 + d * H1 + h);

    float4 acc = make_float4(0.f, 0.f, 0.f, 0.f);
    float den = 0.f;
    int n = end - start;
    const int* cp = g_col + start;

    int i = half;
    for (; i + 2 < n; i += 4) {            // 2 edges per half-warp iteration
        int s0 = __ldg(cp + i);
        int s1 = __ldg(cp + i + 2);
        float e0 = __ldg(g_as1 + s0 * H1 + h) + ad;
        float e1 = __ldg(g_as1 + s1 * H1 + h) + ad;
        e0 = (e0 > 0.f) ? e0 : NEG_SLOPE * e0;
        e1 = (e1 > 0.f) ? e1 : NEG_SLOPE * e1;
        float w0 = __expf(e0);
        float w1 = __expf(e1);
        float4 hv0 = *(const float4*)(g_h1 + (long)s0 * HID + 4 * sl);
        float4 hv1 = *(const float4*)(g_h1 + (long)s1 * HID + 4 * sl);
        den += w0 + w1;
        acc.x += hv0.x * w0 + hv1.x * w1;
        acc.y += hv0.y * w0 + hv1.y * w1;
        acc.z += hv0.z * w0 + hv1.z * w1;
        acc.w += hv0.w * w0 + hv1.w * w1;
    }
    for (; i < n; i += 2) {
        int s0 = __ldg(cp + i);
        float e0 = __ldg(g_as1 + s0 * H1 + h) + ad;
        e0 = (e0 > 0.f) ? e0 : NEG_SLOPE * e0;
        float w0 = __expf(e0);
        float4 hv0 = *(const float4*)(g_h1 + (long)s0 * HID + 4 * sl);
        den += w0;
        acc.x += hv0.x * w0;
        acc.y += hv0.y * w0;
        acc.z += hv0.z * w0;
        acc.w += hv0.w * w0;
    }
    // combine halves
    acc.x += __shfl_xor_sync(0xffffffffu, acc.x, 16);
    acc.y += __shfl_xor_sync(0xffffffffu, acc.y, 16);
    acc.z += __shfl_xor_sync(0xffffffffu, acc.z, 16);
    acc.w += __shfl_xor_sync(0xffffffffu, acc.w, 16);
    den   += __shfl_xor_sync(0xffffffffu, den, 16);

    float inv = 1.0f / den;
    float v0 = acc.x * inv + __ldg(b1 + 4 * sl + 0);
    float v1 = acc.y * inv + __ldg(b1 + 4 * sl + 1);
    float v2 = acc.z * inv + __ldg(b1 + 4 * sl + 2);
    float v3 = acc.w * inv + __ldg(b1 + 4 * sl + 3);
    v0 = (v0 > 0.f) ? v0 : expm1f(v0);
    v1 = (v1 > 0.f) ? v1 : expm1f(v1);
    v2 = (v2 > 0.f) ? v2 : expm1f(v2);
    v3 = (v3 > 0.f) ? v3 : expm1f(v3);
    if (half == 0)
        *(float4*)&hb[wslot][4 * sl] = make_float4(v0, v1, v2, v3);
    __syncwarp();

    // phase B: h2 = h1o @ W2 (lanes 0..19 -> channel pairs), as2/ad2 reduce
    float pa = 0.f, pd = 0.f;
    if (lane < NC / 2) {
        unsigned long long a2 = pack2(0.f, 0.f);
        const float* hr = hb[wslot];
        #pragma unroll 4
        for (int k = 0; k < HID; k++) {
            float xv = hr[k];
            a2 = ffma2(pack2(xv, xv), Wp[k][lane], a2);
        }
        float c0, c1;
        unpack2(a2, c0, c1);
        *(float2*)(g_h2 + (long)d * NC + 2 * lane) = make_float2(c0, c1);
        pa = c0 * Sa[2 * lane] + c1 * Sa[2 * lane + 1];
        pd = c0 * Sd[2 * lane] + c1 * Sd[2 * lane + 1];
    }
    #pragma unroll
    for (int o = 16; o >= 1; o >>= 1) {
        pa += __shfl_xor_sync(0xffffffffu, pa, o);
        pd += __shfl_xor_sync(0xffffffffu, pd, o);
    }
    if (lane == 0) {
        g_as2[d] = pa;
        g_ad2[d] = pd;
    }
}

// ------ layer 2 aggregation: half-warp edge split + log_softmax ---------------
__global__ void k_agg2(const float* __restrict__ b2, float* __restrict__ out) {
    int warp = (blockIdx.x * blockDim.x + threadIdx.x) >> 5;
    int lane = threadIdx.x & 31;
    if (warp >= NN) return;
    int d = warp;
    int start = g_rowptr[d], end = g_rowptr[d + 1];
    float ad = __ldg(g_ad2 + d);
    int half = lane >> 4;
    int sl = lane & 15;
    bool act = sl < 10;                    // 10 sub-lanes x 4 ch = 40

    float4 acc = make_float4(0.f, 0.f, 0.f, 0.f);
    float den = 0.f;
    int n = end - start;
    const int* cp = g_col + start;

    int i = half;
    for (; i + 2 < n; i += 4) {
        int s0 = __ldg(cp + i);
        int s1 = __ldg(cp + i + 2);
        float e0 = __ldg(g_as2 + s0) + ad;
        float e1 = __ldg(g_as2 + s1) + ad;
        e0 = (e0 > 0.f) ? e0 : NEG_SLOPE * e0;
        e1 = (e1 > 0.f) ? e1 : NEG_SLOPE * e1;
        float w0 = __expf(e0);
        float w1 = __expf(e1);
        den += w0 + w1;
        if (act) {
            float4 hv0 = *(const float4*)(g_h2 + (long)s0 * NC + 4 * sl);
            float4 hv1 = *(const float4*)(g_h2 + (long)s1 * NC + 4 * sl);
            acc.x += hv0.x * w0 + hv1.x * w1;
            acc.y += hv0.y * w0 + hv1.y * w1;
            acc.z += hv0.z * w0 + hv1.z * w1;
            acc.w += hv0.w * w0 + hv1.w * w1;
        }
    }
    for (; i < n; i += 2) {
        int s0 = __ldg(cp + i);
        float e0 = __ldg(g_as2 + s0) + ad;
        e0 = (e0 > 0.f) ? e0 : NEG_SLOPE * e0;
        float w0 = __expf(e0);
        den += w0;
        if (act) {
            float4 hv0 = *(const float4*)(g_h2 + (long)s0 * NC + 4 * sl);
            acc.x += hv0.x * w0;
            acc.y += hv0.y * w0;
            acc.z += hv0.z * w0;
            acc.w += hv0.w * w0;
        }
    }
    acc.x += __shfl_xor_sync(0xffffffffu, acc.x, 16);
    acc.y += __shfl_xor_sync(0xffffffffu, acc.y, 16);
    acc.z += __shfl_xor_sync(0xffffffffu, acc.z, 16);
    acc.w += __shfl_xor_sync(0xffffffffu, acc.w, 16);
    den   += __shfl_xor_sync(0xffffffffu, den, 16);

    float inv = 1.0f / den;
    bool mine = (half == 0) && act;        // avoid double counting in softmax
    float v0 = mine ? (acc.x * inv + __ldg(b2 + 4 * sl + 0)) : -3.0e38f;
    float v1 = mine ? (acc.y * inv + __ldg(b2 + 4 * sl + 1)) : -3.0e38f;
    float v2 = mine ? (acc.z * inv + __ldg(b2 + 4 * sl + 2)) : -3.0e38f;
    float v3 = mine ? (acc.w * inv + __ldg(b2 + 4 * sl + 3)) : -3.0e38f;

    float m = fmaxf(fmaxf(v0, v1), fmaxf(v2, v3));
    #pragma unroll
    for (int o = 16; o >= 1; o >>= 1) m = fmaxf(m, __shfl_xor_sync(0xffffffffu, m, o));
    float se = mine ? (__expf(v0 - m) + __expf(v1 - m) + __expf(v2 - m) + __expf(v3 - m)) : 0.f;
    #pragma unroll
    for (int o = 16; o >= 1; o >>= 1) se += __shfl_xor_sync(0xffffffffu, se, o);
    float lse = m + logf(se);

    if (mine)
        *(float4*)(out + (long)d * NC + 4 * sl) =
            make_float4(v0 - lse, v1 - lse, v2 - lse, v3 - lse);
}

// -----------------------------------------------------------------------------
extern "C" void kernel_launch(void* const* d_in, const int* in_sizes, int n_in,
                              void* d_out, int out_size) {
    const float* x        = (const float*)d_in[0];
    const float* W1       = (const float*)d_in[1];
    const float* att_src1 = (const float*)d_in[2];
    const float* att_dst1 = (const float*)d_in[3];
    const float* b1       = (const float*)d_in[4];
    const float* W2       = (const float*)d_in[5];
    const float* att_src2 = (const float*)d_in[6];
    const float* att_dst2 = (const float*)d_in[7];
    const float* b2       = (const float*)d_in[8];
    const void*  ei       = d_in[9];
    float* out = (float*)d_out;

    int EC = in_sizes[9] / 2;
    if (EC > E_MAX) EC = E_MAX;
    int nblocks = (NN + 1023) / 1024;

    cudaStream_t side;
    cudaStreamCreateWithFlags(&side, cudaStreamNonBlocking);
    cudaEvent_t evFork, evJoin;
    cudaEventCreateWithFlags(&evFork, cudaEventDisableTiming);
    cudaEventCreateWithFlags(&evJoin, cudaEventDisableTiming);

    cudaEventRecord(evFork, 0);
    cudaStreamWaitEvent(side, evFork, 0);
    k_gemm1<<<(NN + 127) / 128, 256, 0, side>>>(x, W1, att_src1, att_dst1);
    cudaEventRecord(evJoin, side);

    k_init<<<(NN + 255) / 256, 256>>>(ei, EC);
    k_hist<<<(EC + 255) / 256, 256>>>(ei, EC);
    k_scan_block<<<nblocks, 1024>>>();
    k_scan_tops<<<1, 32>>>(nblocks);
    k_scan_fix<<<nblocks, 1024>>>(EC);
    k_scatter<<<(EC + 255) / 256, 256>>>(ei, EC);

    cudaStreamWaitEvent(0, evJoin, 0);
    k_agg1g2<<<(NN * 32 + 255) / 256, 256>>>(b1, W2, att_src2, att_dst2);
    k_agg2<<<(NN * 32 + 255) / 256, 256>>>(b2, out);
}

// round 13
// speedup vs baseline: 1.4578x; 1.4578x over previous
#include <cuda_runtime.h>
#include <cuda_bf16.h>
#include <math.h>

#define NN      100000
#define F_IN    256
#define HID     64
#define H1      8
#define C1      8
#define NC      40
#define E_MAX   1700000
#define NEG_SLOPE 0.2f
#define AST     132

// ---------------- packed f32x2 helpers ----------------------------------------
__device__ __forceinline__ unsigned long long ffma2(
    unsigned long long a, unsigned long long b, unsigned long long c) {
    unsigned long long d;
    asm("fma.rn.f32x2 %0, %1, %2, %3;" : "=l"(d) : "l"(a), "l"(b), "l"(c));
    return d;
}
__device__ __forceinline__ unsigned long long pack2(float lo, float hi) {
    unsigned long long d;
    asm("mov.b64 %0, {%1, %2};" : "=l"(d) : "f"(lo), "f"(hi));
    return d;
}
__device__ __forceinline__ void unpack2(unsigned long long v, float& lo, float& hi) {
    asm("mov.b64 {%0, %1}, %2;" : "=f"(lo), "=f"(hi) : "l"(v));
}

// ---------------- scratch -----------------------------------------------------
__device__ int   g_is64;
__device__ int   g_deg[NN];
__device__ int   g_rowptr[NN + 1];
__device__ int   g_fill[NN];
__device__ int   g_col[E_MAX];
__device__ int   g_bsum[256];
__device__ float g_h1[(long)NN * HID];
__device__ float g_as1[NN * H1];
__device__ float g_ad1[NN * H1];
__device__ float g_h1o[(long)NN * HID];
__device__ float g_h2[(long)NN * NC];
__device__ float g_as2[NN];
__device__ float g_ad2[NN];

// -------- init: zero degrees + edge dtype detection (block 0) -----------------
__global__ void k_init(const void* ei, int EC) {
    int i = blockIdx.x * blockDim.x + threadIdx.x;
    if (i < NN) g_deg[i] = 0;
    if (blockIdx.x == 0) {
        __shared__ int bad;
        if (threadIdx.x == 0) bad = 0;
        __syncthreads();
        const long long* p = (const long long*)ei;
        int n = EC < 256 ? EC : 256;
        if ((int)threadIdx.x < n) {
            long long v = p[threadIdx.x];
            if (v < 0 || v >= NN) atomicExch(&bad, 1);
        }
        __syncthreads();
        if (threadIdx.x == 0) g_is64 = bad ? 0 : 1;
    }
}

__device__ __forceinline__ int edge_at(const void* ei, int idx) {
    return g_is64 ? (int)((const long long*)ei)[idx] : ((const int*)ei)[idx];
}

// ---------------- CSR build ---------------------------------------------------
__global__ void k_hist(const void* ei, int EC) {
    int i = blockIdx.x * blockDim.x + threadIdx.x;
    if (i < EC) {
        int d = edge_at(ei, EC + i);
        if (d >= 0 && d < NN) atomicAdd(&g_deg[d], 1);
    }
}

__global__ void k_scan_block() {
    __shared__ int ws[32];
    int tid = threadIdx.x;
    int gid = blockIdx.x * 1024 + tid;
    int v = (gid < NN) ? g_deg[gid] : 0;
    int x = v;
    #pragma unroll
    for (int o = 1; o < 32; o <<= 1) {
        int t = __shfl_up_sync(0xffffffffu, x, o);
        if ((tid & 31) >= o) x += t;
    }
    if ((tid & 31) == 31) ws[tid >> 5] = x;
    __syncthreads();
    if (tid < 32) {
        int w = ws[tid];
        int y = w;
        #pragma unroll
        for (int o = 1; o < 32; o <<= 1) {
            int t = __shfl_up_sync(0xffffffffu, y, o);
            if (tid >= o) y += t;
        }
        ws[tid] = y - w;
    }
    __syncthreads();
    int incl = x + ws[tid >> 5];
    if (gid < NN) g_rowptr[gid] = incl - v;
    if (tid == 1023) g_bsum[blockIdx.x] = incl;
}

__global__ void k_scan_tops(int nblocks) {
    int lane = threadIdx.x;
    int run = 0;
    for (int base = 0; base < nblocks; base += 32) {
        int idx = base + lane;
        int v = (idx < nblocks) ? g_bsum[idx] : 0;
        int x = v;
        #pragma unroll
        for (int o = 1; o < 32; o <<= 1) {
            int t = __shfl_up_sync(0xffffffffu, x, o);
            if (lane >= o) x += t;
        }
        if (idx < nblocks) g_bsum[idx] = run + x - v;
        run += __shfl_sync(0xffffffffu, x, 31);
    }
}

__global__ void k_scan_fix(int EC) {
    int gid = blockIdx.x * 1024 + threadIdx.x;
    if (gid < NN) {
        int v = g_rowptr[gid] + g_bsum[gid >> 10];
        g_rowptr[gid] = v;
        g_fill[gid] = v;
    }
    if (gid == 0) g_rowptr[NN] = EC;
}

__global__ void k_scatter(const void* ei, int EC) {
    int i = blockIdx.x * blockDim.x + threadIdx.x;
    if (i < EC) {
        int s = edge_at(ei, i);
        int d = edge_at(ei, EC + i);
        if (d >= 0 && d < NN) {
            int p = atomicAdd(&g_fill[d], 1);
            if (p >= 0 && p < E_MAX) g_col[p] = s;
        }
    }
}

// ------- GEMM1: 128x64 tile, FFMA2 inner, double-buffered (1 sync/iter) -------
__global__ void __launch_bounds__(256) k_gemm1(
    const float* __restrict__ X, const float* __restrict__ W,
    const float* __restrict__ att_s, const float* __restrict__ att_d) {
    __shared__ __align__(16) float smA[2][32 * AST];   // transposed [kk][row]
    __shared__ __align__(16) float smB[2][32 * 64];
    int tid = threadIdx.x;
    int r0 = blockIdx.x * 128;
    int tx = tid & 15, ty = tid >> 4;

    unsigned long long acc2[4][4];
    unsigned long long z = pack2(0.f, 0.f);
    #pragma unroll
    for (int p = 0; p < 4; p++)
        #pragma unroll
        for (int c = 0; c < 4; c++) acc2[p][c] = z;

    // per-thread staging registers
    float4 va[4], vb[2];
    int arow[4], af4[4], bkk[2], bcv[2];
    #pragma unroll
    for (int l = 0; l < 4; l++) {
        int slot = tid + l * 256;
        arow[l] = slot >> 3;
        af4[l] = slot & 7;
    }
    #pragma unroll
    for (int l = 0; l < 2; l++) {
        int slot = tid + l * 256;
        bkk[l] = slot >> 4;
        bcv[l] = slot & 15;
    }

    auto load_regs = [&](int k0) {
        #pragma unroll
        for (int l = 0; l < 4; l++) {
            int gr = r0 + arow[l];
            va[l] = make_float4(0.f, 0.f, 0.f, 0.f);
            if (gr < NN) va[l] = *(const float4*)(X + (long)gr * F_IN + k0 + af4[l] * 4);
        }
        #pragma unroll
        for (int l = 0; l < 2; l++)
            vb[l] = *(const float4*)(W + (k0 + bkk[l]) * HID + bcv[l] * 4);
    };
    auto store_regs = [&](int st) {
        float* As = smA[st];
        float* Bs = smB[st];
        #pragma unroll
        for (int l = 0; l < 4; l++) {
            As[(af4[l] * 4 + 0) * AST + arow[l]] = va[l].x;
            As[(af4[l] * 4 + 1) * AST + arow[l]] = va[l].y;
            As[(af4[l] * 4 + 2) * AST + arow[l]] = va[l].z;
            As[(af4[l] * 4 + 3) * AST + arow[l]] = va[l].w;
        }
        #pragma unroll
        for (int l = 0; l < 2; l++)
            *(float4*)&Bs[bkk[l] * 64 + bcv[l] * 4] = vb[l];
    };

    load_regs(0);
    store_regs(0);
    __syncthreads();

    #pragma unroll 1
    for (int it = 0; it < F_IN / 32; it++) {
        if (it + 1 < F_IN / 32) load_regs((it + 1) * 32);   // LDG in flight
        const float* As = smA[it & 1];
        const float* Bs = smB[it & 1];
        #pragma unroll
        for (int kk = 0; kk < 32; kk++) {
            float4 bv = *(const float4*)&Bs[kk * 64 + tx * 4];
            unsigned long long br[4];
            br[0] = pack2(bv.x, bv.x);
            br[1] = pack2(bv.y, bv.y);
            br[2] = pack2(bv.z, bv.z);
            br[3] = pack2(bv.w, bv.w);
            const float* ab = As + kk * AST + ty * 8;
            #pragma unroll
            for (int p = 0; p < 4; p++) {
                unsigned long long ap = *(const unsigned long long*)(ab + 2 * p);
                acc2[p][0] = ffma2(ap, br[0], acc2[p][0]);
                acc2[p][1] = ffma2(ap, br[1], acc2[p][1]);
                acc2[p][2] = ffma2(ap, br[2], acc2[p][2]);
                acc2[p][3] = ffma2(ap, br[3], acc2[p][3]);
            }
        }
        if (it + 1 < F_IN / 32) {
            store_regs((it + 1) & 1);   // other stage: WAR-safe (see analysis)
            __syncthreads();            // single sync per iteration
        }
    }
    __syncthreads();   // before reusing smA as hbuf

    float* hbuf = smA[0];             // [128][65] fits in 2*32*AST floats
    #pragma unroll
    for (int p = 0; p < 4; p++) {
        float lo[4], hi[4];
        #pragma unroll
        for (int c = 0; c < 4; c++) unpack2(acc2[p][c], lo[c], hi[c]);
        int lr = ty * 8 + 2 * p;
        int gr = r0 + lr;
        #pragma unroll
        for (int c = 0; c < 4; c++) {
            hbuf[lr * 65 + tx * 4 + c] = lo[c];
            hbuf[(lr + 1) * 65 + tx * 4 + c] = hi[c];
        }
        if (gr < NN) {
            #pragma unroll
            for (int c = 0; c < 4; c++)
                g_h1[(long)gr * HID + tx * 4 + c] = lo[c];
        }
        if (gr + 1 < NN) {
            #pragma unroll
            for (int c = 0; c < 4; c++)
                g_h1[(long)(gr + 1) * HID + tx * 4 + c] = hi[c];
        }
    }
    __syncthreads();

    #pragma unroll
    for (int t = 0; t < 4; t++) {
        int item = tid + t * 256;
        int lr = item >> 3, h = item & 7;
        int gr = r0 + lr;
        if (gr < NN) {
            const float* hp = hbuf + lr * 65 + h * C1;
            float as = 0.f, ad = 0.f;
            #pragma unroll
            for (int c = 0; c < C1; c++) {
                float hv = hp[c];
                as += hv * __ldg(att_s + h * C1 + c);
                ad += hv * __ldg(att_d + h * C1 + c);
            }
            g_as1[gr * H1 + h] = as;
            g_ad1[gr * H1 + h] = ad;
        }
    }
}

// -------- layer 1 aggregation (R7 final form): shfl-free, 2-edge ILP + elu ----
__global__ void k_agg1(const float* __restrict__ b1) {
    int warp = (blockIdx.x * blockDim.x + threadIdx.x) >> 5;
    int lane = threadIdx.x & 31;
    if (warp >= NN) return;
    int d = warp;
    int start = g_rowptr[d], end = g_rowptr[d + 1];
    int h = lane >> 2;
    float ad = __ldg(g_ad1 + d * H1 + h);

    unsigned long long acc = pack2(0.f, 0.f);
    float den = 0.f;
    int n = end - start;
    int n2 = n & ~1;
    const int* cp = g_col + start;

    #pragma unroll 2
    for (int i = 0; i < n2; i += 2) {
        int s0 = __ldg(cp + i);
        int s1 = __ldg(cp + i + 1);
        float e0 = __ldg(g_as1 + s0 * H1 + h) + ad;
        float e1 = __ldg(g_as1 + s1 * H1 + h) + ad;
        e0 = (e0 > 0.f) ? e0 : NEG_SLOPE * e0;
        e1 = (e1 > 0.f) ? e1 : NEG_SLOPE * e1;
        float w0 = __expf(e0);
        float w1 = __expf(e1);
        unsigned long long hv0 = *(const unsigned long long*)(g_h1 + (long)s0 * HID + 2 * lane);
        unsigned long long hv1 = *(const unsigned long long*)(g_h1 + (long)s1 * HID + 2 * lane);
        den += w0 + w1;
        acc = ffma2(hv0, pack2(w0, w0), acc);
        acc = ffma2(hv1, pack2(w1, w1), acc);
    }
    if (n2 < n) {
        int s0 = __ldg(cp + n2);
        float e0 = __ldg(g_as1 + s0 * H1 + h) + ad;
        e0 = (e0 > 0.f) ? e0 : NEG_SLOPE * e0;
        float w0 = __expf(e0);
        unsigned long long hv0 = *(const unsigned long long*)(g_h1 + (long)s0 * HID + 2 * lane);
        den += w0;
        acc = ffma2(hv0, pack2(w0, w0), acc);
    }
    float inv = 1.0f / den;
    float lo, hi;
    unpack2(acc, lo, hi);
    float v0 = lo * inv + __ldg(b1 + 2 * lane);
    float v1 = hi * inv + __ldg(b1 + 2 * lane + 1);
    v0 = (v0 > 0.f) ? v0 : expm1f(v0);
    v1 = (v1 > 0.f) ? v1 : expm1f(v1);
    *(float2*)(g_h1o + (long)d * HID + 2 * lane) = make_float2(v0, v1);
}

// ---------------- GEMM2 (R7 form: FFMA2 inner) + alpha2 -----------------------
__global__ void __launch_bounds__(128) k_gemm2(
    const float* __restrict__ W2,
    const float* __restrict__ att_s2, const float* __restrict__ att_d2) {
    __shared__ __align__(16) float Xs[128][65];
    __shared__ __align__(16) float Ws[HID][NC];
    __shared__ float Sa[NC], Sd[NC];
    int tid = threadIdx.x;
    int r0 = blockIdx.x * 128;
    for (int f = tid; f < HID * NC; f += 128) Ws[f / NC][f % NC] = W2[f];
    if (tid < NC) { Sa[tid] = att_s2[tid]; Sd[tid] = att_d2[tid]; }
    for (int f = tid; f < 128 * HID; f += 128) {
        int rr = f >> 6, cc = f & 63;
        int gr = r0 + rr;
        Xs[rr][cc] = (gr < NN) ? g_h1o[(long)gr * HID + cc] : 0.f;
    }
    __syncthreads();
    int r = r0 + tid;
    unsigned long long acc2[NC / 2];
    unsigned long long z = pack2(0.f, 0.f);
    #pragma unroll
    for (int c = 0; c < NC / 2; c++) acc2[c] = z;
    #pragma unroll 4
    for (int k = 0; k < HID; k++) {
        float xv = Xs[tid][k];
        unsigned long long xp = pack2(xv, xv);
        const unsigned long long* wp = (const unsigned long long*)&Ws[k][0];
        #pragma unroll
        for (int c = 0; c < NC / 2; c++) acc2[c] = ffma2(xp, wp[c], acc2[c]);
    }
    if (r < NN) {
        float a = 0.f, dd = 0.f;
        #pragma unroll
        for (int c = 0; c < NC / 2; c++) {
            float lo, hi;
            unpack2(acc2[c], lo, hi);
            g_h2[(long)r * NC + 2 * c]     = lo;
            g_h2[(long)r * NC + 2 * c + 1] = hi;
            a  += lo * Sa[2 * c] + hi * Sa[2 * c + 1];
            dd += lo * Sd[2 * c] + hi * Sd[2 * c + 1];
        }
        g_as2[r] = a;
        g_ad2[r] = dd;
    }
}

// --------- layer 2 aggregation (R7 final form) + log_softmax ------------------
__global__ void k_agg2(const float* __restrict__ b2, float* __restrict__ out) {
    int warp = (blockIdx.x * blockDim.x + threadIdx.x) >> 5;
    int lane = threadIdx.x & 31;
    if (warp >= NN) return;
    int d = warp;
    int start = g_rowptr[d], end = g_rowptr[d + 1];
    float ad = __ldg(g_ad2 + d);
    bool act = lane < 20;

    unsigned long long acc = pack2(0.f, 0.f);
    float den = 0.f;
    int n = end - start;
    int n2 = n & ~1;
    const int* cp = g_col + start;

    #pragma unroll 2
    for (int i = 0; i < n2; i += 2) {
        int s0 = __ldg(cp + i);
        int s1 = __ldg(cp + i + 1);
        float e0 = __ldg(g_as2 + s0) + ad;
        float e1 = __ldg(g_as2 + s1) + ad;
        e0 = (e0 > 0.f) ? e0 : NEG_SLOPE * e0;
        e1 = (e1 > 0.f) ? e1 : NEG_SLOPE * e1;
        float w0 = __expf(e0);
        float w1 = __expf(e1);
        den += w0 + w1;
        if (act) {
            unsigned long long hv0 = *(const unsigned long long*)(g_h2 + (long)s0 * NC + 2 * lane);
            unsigned long long hv1 = *(const unsigned long long*)(g_h2 + (long)s1 * NC + 2 * lane);
            acc = ffma2(hv0, pack2(w0, w0), acc);
            acc = ffma2(hv1, pack2(w1, w1), acc);
        }
    }
    if (n2 < n) {
        int s0 = __ldg(cp + n2);
        float e0 = __ldg(g_as2 + s0) + ad;
        e0 = (e0 > 0.f) ? e0 : NEG_SLOPE * e0;
        float w0 = __expf(e0);
        den += w0;
        if (act) {
            unsigned long long hv0 = *(const unsigned long long*)(g_h2 + (long)s0 * NC + 2 * lane);
            acc = ffma2(hv0, pack2(w0, w0), acc);
        }
    }
    float inv = 1.0f / den;
    float lo, hi;
    unpack2(acc, lo, hi);
    float v0 = act ? (lo * inv + __ldg(b2 + 2 * lane))     : -3.0e38f;
    float v1 = act ? (hi * inv + __ldg(b2 + 2 * lane + 1)) : -3.0e38f;

    float m = fmaxf(v0, v1);
    #pragma unroll
    for (int o = 16; o >= 1; o >>= 1) m = fmaxf(m, __shfl_xor_sync(0xffffffffu, m, o));
    float se = act ? (__expf(v0 - m) + __expf(v1 - m)) : 0.f;
    #pragma unroll
    for (int o = 16; o >= 1; o >>= 1) se += __shfl_xor_sync(0xffffffffu, se, o);
    float lse = m + logf(se);

    if (act)
        *(float2*)(out + (long)d * NC + 2 * lane) = make_float2(v0 - lse, v1 - lse);
}

// -----------------------------------------------------------------------------
extern "C" void kernel_launch(void* const* d_in, const int* in_sizes, int n_in,
                              void* d_out, int out_size) {
    const float* x        = (const float*)d_in[0];
    const float* W1       = (const float*)d_in[1];
    const float* att_src1 = (const float*)d_in[2];
    const float* att_dst1 = (const float*)d_in[3];
    const float* b1       = (const float*)d_in[4];
    const float* W2       = (const float*)d_in[5];
    const float* att_src2 = (const float*)d_in[6];
    const float* att_dst2 = (const float*)d_in[7];
    const float* b2       = (const float*)d_in[8];
    const void*  ei       = d_in[9];
    float* out = (float*)d_out;

    int EC = in_sizes[9] / 2;
    if (EC > E_MAX) EC = E_MAX;
    int nblocks = (NN + 1023) / 1024;

    cudaStream_t side;
    cudaStreamCreateWithFlags(&side, cudaStreamNonBlocking);
    cudaEvent_t evFork, evJoin;
    cudaEventCreateWithFlags(&evFork, cudaEventDisableTiming);
    cudaEventCreateWithFlags(&evJoin, cudaEventDisableTiming);

    cudaEventRecord(evFork, 0);
    cudaStreamWaitEvent(side, evFork, 0);
    k_gemm1<<<(NN + 127) / 128, 256, 0, side>>>(x, W1, att_src1, att_dst1);
    cudaEventRecord(evJoin, side);

    k_init<<<(NN + 255) / 256, 256>>>(ei, EC);
    k_hist<<<(EC + 255) / 256, 256>>>(ei, EC);
    k_scan_block<<<nblocks, 1024>>>();
    k_scan_tops<<<1, 32>>>(nblocks);
    k_scan_fix<<<nblocks, 1024>>>(EC);
    k_scatter<<<(EC + 255) / 256, 256>>>(ei, EC);

    cudaStreamWaitEvent(0, evJoin, 0);
    k_agg1<<<(NN * 32 + 255) / 256, 256>>>(b1);
    k_gemm2<<<(NN + 127) / 128, 128>>>(W2, att_src2, att_dst2);
    k_agg2<<<(NN * 32 + 255) / 256, 256>>>(b2, out);
}

// round 14
// speedup vs baseline: 1.5058x; 1.0330x over previous
#include <cuda_runtime.h>
#include <cuda_bf16.h>
#include <math.h>

#define NN      100000
#define F_IN    256
#define HID     64
#define H1      8
#define C1      8
#define NC      40
#define E_MAX   1700000
#define NEG_SLOPE 0.2f
#define AST     132
#define NA      50048     // first-half node count (multiple of 128)

// ---------------- packed f32x2 helpers ----------------------------------------
__device__ __forceinline__ unsigned long long ffma2(
    unsigned long long a, unsigned long long b, unsigned long long c) {
    unsigned long long d;
    asm("fma.rn.f32x2 %0, %1, %2, %3;" : "=l"(d) : "l"(a), "l"(b), "l"(c));
    return d;
}
__device__ __forceinline__ unsigned long long pack2(float lo, float hi) {
    unsigned long long d;
    asm("mov.b64 %0, {%1, %2};" : "=l"(d) : "f"(lo), "f"(hi));
    return d;
}
__device__ __forceinline__ void unpack2(unsigned long long v, float& lo, float& hi) {
    asm("mov.b64 {%0, %1}, %2;" : "=f"(lo), "=f"(hi) : "l"(v));
}

// ---------------- scratch -----------------------------------------------------
__device__ int   g_is64;
__device__ int   g_deg[NN];
__device__ int   g_rowptr[NN + 1];
__device__ int   g_fill[NN];
__device__ int   g_col[E_MAX];
__device__ int   g_bsum[256];
__device__ float g_h1[(long)NN * HID];
__device__ float g_as1[NN * H1];
__device__ float g_ad1[NN * H1];
__device__ float g_h1o[(long)NN * HID];
__device__ float g_h2[(long)NN * NC];
__device__ float g_as2[NN];
__device__ float g_ad2[NN];

// -------- init: edge dtype detection only (deg zeroed by memset node) ---------
__global__ void k_detect(const void* ei, int EC) {
    __shared__ int bad;
    if (threadIdx.x == 0) bad = 0;
    __syncthreads();
    const long long* p = (const long long*)ei;
    int n = EC < 256 ? EC : 256;
    if ((int)threadIdx.x < n) {
        long long v = p[threadIdx.x];
        if (v < 0 || v >= NN) atomicExch(&bad, 1);
    }
    __syncthreads();
    if (threadIdx.x == 0) g_is64 = bad ? 0 : 1;
}

__device__ __forceinline__ int edge_at(const void* ei, int idx) {
    return g_is64 ? (int)((const long long*)ei)[idx] : ((const int*)ei)[idx];
}

// ---------------- CSR build ---------------------------------------------------
__global__ void k_hist(const void* ei, int EC) {
    int i = blockIdx.x * blockDim.x + threadIdx.x;
    if (i < EC) {
        int d = edge_at(ei, EC + i);
        if (d >= 0 && d < NN) atomicAdd(&g_deg[d], 1);
    }
}

__global__ void k_scan_block() {
    __shared__ int ws[32];
    int tid = threadIdx.x;
    int gid = blockIdx.x * 1024 + tid;
    int v = (gid < NN) ? g_deg[gid] : 0;
    int x = v;
    #pragma unroll
    for (int o = 1; o < 32; o <<= 1) {
        int t = __shfl_up_sync(0xffffffffu, x, o);
        if ((tid & 31) >= o) x += t;
    }
    if ((tid & 31) == 31) ws[tid >> 5] = x;
    __syncthreads();
    if (tid < 32) {
        int w = ws[tid];
        int y = w;
        #pragma unroll
        for (int o = 1; o < 32; o <<= 1) {
            int t = __shfl_up_sync(0xffffffffu, y, o);
            if (tid >= o) y += t;
        }
        ws[tid] = y - w;
    }
    __syncthreads();
    int incl = x + ws[tid >> 5];
    if (gid < NN) g_rowptr[gid] = incl - v;
    if (tid == 1023) g_bsum[blockIdx.x] = incl;
}

__global__ void k_scan_tops(int nblocks) {
    int lane = threadIdx.x;
    int run = 0;
    for (int base = 0; base < nblocks; base += 32) {
        int idx = base + lane;
        int v = (idx < nblocks) ? g_bsum[idx] : 0;
        int x = v;
        #pragma unroll
        for (int o = 1; o < 32; o <<= 1) {
            int t = __shfl_up_sync(0xffffffffu, x, o);
            if (lane >= o) x += t;
        }
        if (idx < nblocks) g_bsum[idx] = run + x - v;
        run += __shfl_sync(0xffffffffu, x, 31);
    }
}

__global__ void k_scan_fix(int EC) {
    int gid = blockIdx.x * 1024 + threadIdx.x;
    if (gid < NN) {
        int v = g_rowptr[gid] + g_bsum[gid >> 10];
        g_rowptr[gid] = v;
        g_fill[gid] = v;
    }
    if (gid == 0) g_rowptr[NN] = EC;
}

__global__ void k_scatter(const void* ei, int EC) {
    int i = blockIdx.x * blockDim.x + threadIdx.x;
    if (i < EC) {
        int s = edge_at(ei, i);
        int d = edge_at(ei, EC + i);
        if (d >= 0 && d < NN) {
            int p = atomicAdd(&g_fill[d], 1);
            if (p >= 0 && p < E_MAX) g_col[p] = s;
        }
    }
}

// ------- GEMM1 (R7 form: 128x64 tile, FFMA2 inner) + fused alpha epilogue -----
__global__ void __launch_bounds__(256) k_gemm1(
    const float* __restrict__ X, const float* __restrict__ W,
    const float* __restrict__ att_s, const float* __restrict__ att_d) {
    __shared__ __align__(16) float sm[128 * 65];
    float* Ast = sm;
    float* Bs  = sm + 32 * AST;
    int tid = threadIdx.x;
    int r0 = blockIdx.x * 128;
    int tx = tid & 15, ty = tid >> 4;

    unsigned long long acc2[4][4];
    unsigned long long z = pack2(0.f, 0.f);
    #pragma unroll
    for (int p = 0; p < 4; p++)
        #pragma unroll
        for (int c = 0; c < 4; c++) acc2[p][c] = z;

    for (int k0 = 0; k0 < F_IN; k0 += 32) {
        #pragma unroll
        for (int l = 0; l < 4; l++) {
            int slot = tid + l * 256;
            int row = slot >> 3;
            int f4 = slot & 7;
            int gr = r0 + row;
            float4 v = make_float4(0.f, 0.f, 0.f, 0.f);
            if (gr < NN) v = *(const float4*)(X + (long)gr * F_IN + k0 + f4 * 4);
            Ast[(f4 * 4 + 0) * AST + row] = v.x;
            Ast[(f4 * 4 + 1) * AST + row] = v.y;
            Ast[(f4 * 4 + 2) * AST + row] = v.z;
            Ast[(f4 * 4 + 3) * AST + row] = v.w;
        }
        #pragma unroll
        for (int l = 0; l < 2; l++) {
            int slot = tid + l * 256;
            int kk = slot >> 4;
            int cv = slot & 15;
            *(float4*)&Bs[kk * 64 + cv * 4] = *(const float4*)(W + (k0 + kk) * HID + cv * 4);
        }
        __syncthreads();
        #pragma unroll
        for (int kk = 0; kk < 32; kk++) {
            float4 bv = *(const float4*)&Bs[kk * 64 + tx * 4];
            unsigned long long br[4];
            br[0] = pack2(bv.x, bv.x);
            br[1] = pack2(bv.y, bv.y);
            br[2] = pack2(bv.z, bv.z);
            br[3] = pack2(bv.w, bv.w);
            const float* ab = Ast + kk * AST + ty * 8;
            #pragma unroll
            for (int p = 0; p < 4; p++) {
                unsigned long long ap = *(const unsigned long long*)(ab + 2 * p);
                acc2[p][0] = ffma2(ap, br[0], acc2[p][0]);
                acc2[p][1] = ffma2(ap, br[1], acc2[p][1]);
                acc2[p][2] = ffma2(ap, br[2], acc2[p][2]);
                acc2[p][3] = ffma2(ap, br[3], acc2[p][3]);
            }
        }
        __syncthreads();
    }

    float* hbuf = sm;
    #pragma unroll
    for (int p = 0; p < 4; p++) {
        float lo[4], hi[4];
        #pragma unroll
        for (int c = 0; c < 4; c++) unpack2(acc2[p][c], lo[c], hi[c]);
        int lr = ty * 8 + 2 * p;
        int gr = r0 + lr;
        #pragma unroll
        for (int c = 0; c < 4; c++) {
            hbuf[lr * 65 + tx * 4 + c] = lo[c];
            hbuf[(lr + 1) * 65 + tx * 4 + c] = hi[c];
        }
        if (gr < NN) {
            #pragma unroll
            for (int c = 0; c < 4; c++)
                g_h1[(long)gr * HID + tx * 4 + c] = lo[c];
        }
        if (gr + 1 < NN) {
            #pragma unroll
            for (int c = 0; c < 4; c++)
                g_h1[(long)(gr + 1) * HID + tx * 4 + c] = hi[c];
        }
    }
    __syncthreads();

    #pragma unroll
    for (int t = 0; t < 4; t++) {
        int item = tid + t * 256;
        int lr = item >> 3, h = item & 7;
        int gr = r0 + lr;
        if (gr < NN) {
            const float* hp = hbuf + lr * 65 + h * C1;
            float as = 0.f, ad = 0.f;
            #pragma unroll
            for (int c = 0; c < C1; c++) {
                float hv = hp[c];
                as += hv * __ldg(att_s + h * C1 + c);
                ad += hv * __ldg(att_d + h * C1 + c);
            }
            g_as1[gr * H1 + h] = as;
            g_ad1[gr * H1 + h] = ad;
        }
    }
}

// -------- layer 1 aggregation (R7 final form), node range [base, base+count) --
__global__ void k_agg1(const float* __restrict__ b1, int base, int count) {
    int warp = (blockIdx.x * blockDim.x + threadIdx.x) >> 5;
    int lane = threadIdx.x & 31;
    if (warp >= count) return;
    int d = base + warp;
    int start = g_rowptr[d], end = g_rowptr[d + 1];
    int h = lane >> 2;
    float ad = __ldg(g_ad1 + d * H1 + h);

    unsigned long long acc = pack2(0.f, 0.f);
    float den = 0.f;
    int n = end - start;
    int n2 = n & ~1;
    const int* cp = g_col + start;

    #pragma unroll 2
    for (int i = 0; i < n2; i += 2) {
        int s0 = __ldg(cp + i);
        int s1 = __ldg(cp + i + 1);
        float e0 = __ldg(g_as1 + s0 * H1 + h) + ad;
        float e1 = __ldg(g_as1 + s1 * H1 + h) + ad;
        e0 = (e0 > 0.f) ? e0 : NEG_SLOPE * e0;
        e1 = (e1 > 0.f) ? e1 : NEG_SLOPE * e1;
        float w0 = __expf(e0);
        float w1 = __expf(e1);
        unsigned long long hv0 = *(const unsigned long long*)(g_h1 + (long)s0 * HID + 2 * lane);
        unsigned long long hv1 = *(const unsigned long long*)(g_h1 + (long)s1 * HID + 2 * lane);
        den += w0 + w1;
        acc = ffma2(hv0, pack2(w0, w0), acc);
        acc = ffma2(hv1, pack2(w1, w1), acc);
    }
    if (n2 < n) {
        int s0 = __ldg(cp + n2);
        float e0 = __ldg(g_as1 + s0 * H1 + h) + ad;
        e0 = (e0 > 0.f) ? e0 : NEG_SLOPE * e0;
        float w0 = __expf(e0);
        unsigned long long hv0 = *(const unsigned long long*)(g_h1 + (long)s0 * HID + 2 * lane);
        den += w0;
        acc = ffma2(hv0, pack2(w0, w0), acc);
    }
    float inv = 1.0f / den;
    float lo, hi;
    unpack2(acc, lo, hi);
    float v0 = lo * inv + __ldg(b1 + 2 * lane);
    float v1 = hi * inv + __ldg(b1 + 2 * lane + 1);
    v0 = (v0 > 0.f) ? v0 : expm1f(v0);
    v1 = (v1 > 0.f) ? v1 : expm1f(v1);
    *(float2*)(g_h1o + (long)d * HID + 2 * lane) = make_float2(v0, v1);
}

// ---------------- GEMM2 (R7 form) + alpha2, node range ------------------------
__global__ void __launch_bounds__(128) k_gemm2(
    const float* __restrict__ W2,
    const float* __restrict__ att_s2, const float* __restrict__ att_d2,
    int base, int count) {
    __shared__ __align__(16) float Xs[128][65];
    __shared__ __align__(16) float Ws[HID][NC];
    __shared__ float Sa[NC], Sd[NC];
    int tid = threadIdx.x;
    int r0 = base + blockIdx.x * 128;
    int rend = base + count;
    for (int f = tid; f < HID * NC; f += 128) Ws[f / NC][f % NC] = W2[f];
    if (tid < NC) { Sa[tid] = att_s2[tid]; Sd[tid] = att_d2[tid]; }
    for (int f = tid; f < 128 * HID; f += 128) {
        int rr = f >> 6, cc = f & 63;
        int gr = r0 + rr;
        Xs[rr][cc] = (gr < rend) ? g_h1o[(long)gr * HID + cc] : 0.f;
    }
    __syncthreads();
    int r = r0 + tid;
    unsigned long long acc2[NC / 2];
    unsigned long long z = pack2(0.f, 0.f);
    #pragma unroll
    for (int c = 0; c < NC / 2; c++) acc2[c] = z;
    #pragma unroll 4
    for (int k = 0; k < HID; k++) {
        float xv = Xs[tid][k];
        unsigned long long xp = pack2(xv, xv);
        const unsigned long long* wp = (const unsigned long long*)&Ws[k][0];
        #pragma unroll
        for (int c = 0; c < NC / 2; c++) acc2[c] = ffma2(xp, wp[c], acc2[c]);
    }
    if (r < rend) {
        float a = 0.f, dd = 0.f;
        #pragma unroll
        for (int c = 0; c < NC / 2; c++) {
            float lo, hi;
            unpack2(acc2[c], lo, hi);
            g_h2[(long)r * NC + 2 * c]     = lo;
            g_h2[(long)r * NC + 2 * c + 1] = hi;
            a  += lo * Sa[2 * c] + hi * Sa[2 * c + 1];
            dd += lo * Sd[2 * c] + hi * Sd[2 * c + 1];
        }
        g_as2[r] = a;
        g_ad2[r] = dd;
    }
}

// --------- layer 2 aggregation (R7 final form) + log_softmax ------------------
__global__ void k_agg2(const float* __restrict__ b2, float* __restrict__ out) {
    int warp = (blockIdx.x * blockDim.x + threadIdx.x) >> 5;
    int lane = threadIdx.x & 31;
    if (warp >= NN) return;
    int d = warp;
    int start = g_rowptr[d], end = g_rowptr[d + 1];
    float ad = __ldg(g_ad2 + d);
    bool act = lane < 20;

    unsigned long long acc = pack2(0.f, 0.f);
    float den = 0.f;
    int n = end - start;
    int n2 = n & ~1;
    const int* cp = g_col + start;

    #pragma unroll 2
    for (int i = 0; i < n2; i += 2) {
        int s0 = __ldg(cp + i);
        int s1 = __ldg(cp + i + 1);
        float e0 = __ldg(g_as2 + s0) + ad;
        float e1 = __ldg(g_as2 + s1) + ad;
        e0 = (e0 > 0.f) ? e0 : NEG_SLOPE * e0;
        e1 = (e1 > 0.f) ? e1 : NEG_SLOPE * e1;
        float w0 = __expf(e0);
        float w1 = __expf(e1);
        den += w0 + w1;
        if (act) {
            unsigned long long hv0 = *(const unsigned long long*)(g_h2 + (long)s0 * NC + 2 * lane);
            unsigned long long hv1 = *(const unsigned long long*)(g_h2 + (long)s1 * NC + 2 * lane);
            acc = ffma2(hv0, pack2(w0, w0), acc);
            acc = ffma2(hv1, pack2(w1, w1), acc);
        }
    }
    if (n2 < n) {
        int s0 = __ldg(cp + n2);
        float e0 = __ldg(g_as2 + s0) + ad;
        e0 = (e0 > 0.f) ? e0 : NEG_SLOPE * e0;
        float w0 = __expf(e0);
        den += w0;
        if (act) {
            unsigned long long hv0 = *(const unsigned long long*)(g_h2 + (long)s0 * NC + 2 * lane);
            acc = ffma2(hv0, pack2(w0, w0), acc);
        }
    }
    float inv = 1.0f / den;
    float lo, hi;
    unpack2(acc, lo, hi);
    float v0 = act ? (lo * inv + __ldg(b2 + 2 * lane))     : -3.0e38f;
    float v1 = act ? (hi * inv + __ldg(b2 + 2 * lane + 1)) : -3.0e38f;

    float m = fmaxf(v0, v1);
    #pragma unroll
    for (int o = 16; o >= 1; o >>= 1) m = fmaxf(m, __shfl_xor_sync(0xffffffffu, m, o));
    float se = act ? (__expf(v0 - m) + __expf(v1 - m)) : 0.f;
    #pragma unroll
    for (int o = 16; o >= 1; o >>= 1) se += __shfl_xor_sync(0xffffffffu, se, o);
    float lse = m + logf(se);

    if (act)
        *(float2*)(out + (long)d * NC + 2 * lane) = make_float2(v0 - lse, v1 - lse);
}

// -----------------------------------------------------------------------------
extern "C" void kernel_launch(void* const* d_in, const int* in_sizes, int n_in,
                              void* d_out, int out_size) {
    const float* x        = (const float*)d_in[0];
    const float* W1       = (const float*)d_in[1];
    const float* att_src1 = (const float*)d_in[2];
    const float* att_dst1 = (const float*)d_in[3];
    const float* b1       = (const float*)d_in[4];
    const float* W2       = (const float*)d_in[5];
    const float* att_src2 = (const float*)d_in[6];
    const float* att_dst2 = (const float*)d_in[7];
    const float* b2       = (const float*)d_in[8];
    const void*  ei       = d_in[9];
    float* out = (float*)d_out;

    int EC = in_sizes[9] / 2;
    if (EC > E_MAX) EC = E_MAX;
    int nblocks = (NN + 1023) / 1024;
    const int NB2 = NN - NA;

    cudaStream_t side;
    cudaStreamCreateWithFlags(&side, cudaStreamNonBlocking);
    cudaEvent_t evFork, evJoin, evA, evG;
    cudaEventCreateWithFlags(&evFork, cudaEventDisableTiming);
    cudaEventCreateWithFlags(&evJoin, cudaEventDisableTiming);
    cudaEventCreateWithFlags(&evA, cudaEventDisableTiming);
    cudaEventCreateWithFlags(&evG, cudaEventDisableTiming);

    // fork: gemm1 on side stream, CSR on main
    cudaEventRecord(evFork, 0);
    cudaStreamWaitEvent(side, evFork, 0);
    k_gemm1<<<(NN + 127) / 128, 256, 0, side>>>(x, W1, att_src1, att_dst1);
    cudaEventRecord(evJoin, side);

    void* degPtr = nullptr;
    cudaGetSymbolAddress(&degPtr, g_deg);
    cudaMemsetAsync(degPtr, 0, NN * sizeof(int), 0);
    k_detect<<<1, 256>>>(ei, EC);
    k_hist<<<(EC + 255) / 256, 256>>>(ei, EC);
    k_scan_block<<<nblocks, 1024>>>();
    k_scan_tops<<<1, 32>>>(nblocks);
    k_scan_fix<<<nblocks, 1024>>>(EC);
    k_scatter<<<(EC + 255) / 256, 256>>>(ei, EC);

    // join; pipelined tail: gemm2(A) on side overlaps agg1(B) on main
    cudaStreamWaitEvent(0, evJoin, 0);
    k_agg1<<<(NA * 32 + 255) / 256, 256>>>(b1, 0, NA);
    cudaEventRecord(evA, 0);
    cudaStreamWaitEvent(side, evA, 0);
    k_gemm2<<<NA / 128, 128, 0, side>>>(W2, att_src2, att_dst2, 0, NA);
    cudaEventRecord(evG, side);

    k_agg1<<<(NB2 * 32 + 255) / 256, 256>>>(b1, NA, NB2);
    k_gemm2<<<(NB2 + 127) / 128, 128>>>(W2, att_src2, att_dst2, NA, NB2);
    cudaStreamWaitEvent(0, evG, 0);
    k_agg2<<<(NN * 32 + 255) / 256, 256>>>(b2, out);
}